// round 6
// baseline (speedup 1.0000x reference)
#include <cuda_runtime.h>
#include <math.h>
#define FULL 0xffffffffu
#define M9 0x1ffu

static constexpr int B=64,T=512,D=768;

__device__ float g_lg1[B*T*2];
__device__ float g_lg2[B*T*9];
__device__ float g_ll1[B],g_ll2[B],g_c1[B],g_c2[B],g_cc[B];
__device__ int g_ctr;

__device__ __forceinline__ unsigned long long ffma2(unsigned long long a,unsigned long long b,unsigned long long c){
    unsigned long long r; asm("fma.rn.f32x2 %0,%1,%2,%3;":"=l"(r):"l"(a),"l"(b),"l"(c)); return r;
}
__device__ __forceinline__ unsigned long long fmul2(unsigned long long a,unsigned long long b){
    unsigned long long r; asm("mul.rn.f32x2 %0,%1,%2;":"=l"(r):"l"(a),"l"(b)); return r;
}
__device__ __forceinline__ unsigned long long pack2(float x){
    unsigned long long r; asm("mov.b64 %0,{%1,%1};":"=l"(r):"f"(x)); return r;
}
__device__ __forceinline__ void unpack2(unsigned long long a,float&lo,float&hi){
    asm("mov.b64 {%0,%1},%2;":"=f"(lo),"=f"(hi):"l"(a));
}

// ---------------- GEMM: row-per-thread streaming, 2 threads/row ----------
__global__ __launch_bounds__(256) void gemm_kernel(const float* __restrict__ x,const float* __restrict__ W1,
    const float* __restrict__ b1,const float* __restrict__ W2,const float* __restrict__ b2){
    __shared__ float wT[11][776];   // halves at +0 / +388 (bank-offset 4)
    __shared__ float bsh[11];
    int tid=threadIdx.x;
    for(int i=tid;i<768*2;i+=256){int d=i>>1,l=i&1;int c=d+((d>=384)?4:0);wT[l][c]=W1[i];}
    for(int i=tid;i<768*9;i+=256){int d=i/9,l=2+(i-d*9);int c=d+((d>=384)?4:0);wT[l][c]=W2[i];}
    if(tid<2)bsh[tid]=b1[tid]; else if(tid<11)bsh[tid]=b2[tid-2];
    __syncthreads();
    int row=blockIdx.x*128+(tid>>1), half=tid&1;
    const ulonglong2* xp=reinterpret_cast<const ulonglong2*>(x+(size_t)row*768+half*384);
    unsigned long long acc[11];
#pragma unroll
    for(int l=0;l<11;l++) acc[l]=0ull;
    int wbase=half*388;
#pragma unroll 3
    for(int it=0;it<12;++it){
        ulonglong2 xv[8];
#pragma unroll
        for(int u=0;u<8;u++) xv[u]=xp[it*8+u];
#pragma unroll
        for(int u=0;u<8;u++){
            int kc=wbase+(it*8+u)*4;
#pragma unroll
            for(int l=0;l<11;l++){
                ulonglong2 wv=*reinterpret_cast<const ulonglong2*>(&wT[l][kc]);
                acc[l]=ffma2(xv[u].x,wv.x,acc[l]);
                acc[l]=ffma2(xv[u].y,wv.y,acc[l]);
            }
        }
    }
    float r[11];
#pragma unroll
    for(int l=0;l<11;l++){
        float lo,hi; unpack2(acc[l],lo,hi);
        float v=lo+hi;
        v+=__shfl_xor_sync(FULL,v,1);
        r[l]=v;
    }
    if(half==0){
        g_lg1[row*2+0]=r[0]+bsh[0];
        g_lg1[row*2+1]=r[1]+bsh[1];
#pragma unroll
        for(int l=0;l<9;l++) g_lg2[row*9+l]=r[2+l]+bsh[2+l];
    }
}

// smem byte offsets
static constexpr int SM_LG2=0;        // (T*9+16) floats = 18496
static constexpr int SM_EL2=18496;    // T*12 floats     = 24576 (cols 9-11 zero)
static constexpr int SM_AL2=43072;    // T*12 floats     = 24576
static constexpr int SM_LG1=67648;    // 4096
static constexpr int SM_EL1=71744;    // 4096
static constexpr int SM_TR2=75840;    // 336
static constexpr int SM_ES =76176;    // 9*10 floats = 360 (pad col 0)
static constexpr int SM_PC =76536;    // 6*81 floats = 1944
static constexpr int SM_BP2=78480;    // 4608
static constexpr int SM_BP1=83088;    // 1024
static constexpr int SM_V1 =84112;    // 512
static constexpr int SM_V2 =84624;    // 512
static constexpr int SM_TOT=85200;

__global__ __launch_bounds__(256) void scan_kernel(const int* __restrict__ label,const int* __restrict__ seqlen,
    const float* __restrict__ trans1,const float* __restrict__ trans2,float* __restrict__ out,int out_size){
    extern __shared__ char sm[];
    float* lg2s=(float*)(sm+SM_LG2);
    float* el2s=(float*)(sm+SM_EL2);
    float* al2s=(float*)(sm+SM_AL2);
    float* lg1s=(float*)(sm+SM_LG1);
    float* el1s=(float*)(sm+SM_EL1);
    float* tr2s=(float*)(sm+SM_TR2);
    float* es  =(float*)(sm+SM_ES);
    float* Pc  =(float*)(sm+SM_PC);
    unsigned char* bp2=(unsigned char*)(sm+SM_BP2);
    uchar2* bp1=(uchar2*)(sm+SM_BP1);
    unsigned char* vit1=(unsigned char*)(sm+SM_V1);
    unsigned char* vit2=(unsigned char*)(sm+SM_V2);
    __shared__ unsigned char map2[63],map1[14],ex2[8],ex1[8];
    __shared__ int s_last2,s_last1,s_isLast,Zc[6];
    __shared__ float s_ln1,s_ln2,s_g1,s_g2,sred[24];

    int b=blockIdx.x, sl=seqlen[b], tid=threadIdx.x, wid=tid>>5, lane=tid&31;
    const int* lab=label+b*T;

    // ---- staging ----
    const float* p2=g_lg2+b*T*9;
    for(int i=tid;i<T*9;i+=256){
        float v=p2[i]; lg2s[i]=v;
        int t=i/9; el2s[t*12+(i-t*9)]=__expf(v);
    }
    for(int i=tid;i<T*3;i+=256){int t=i/3; el2s[t*12+9+(i-t*3)]=0.0f;}
    if(tid<16) lg2s[T*9+tid]=0.0f;
    const float* p1=g_lg1+b*T*2;
    for(int i=tid;i<T*2;i+=256){float v=p1[i]; lg1s[i]=v; el1s[i]=__expf(v);}
    for(int i=tid;i<81;i+=256) tr2s[i]=trans2[i];
    for(int i=tid;i<90;i+=256){int k=i/10,j=i-k*10; es[i]=(j<9)?__expf(trans2[k*9+j]):0.0f;}
    __syncthreads();

    if(wid==0){ // ---- decode2 forward: bit-exact serial, alphas only ----
        if(lane<9){
            int j=lane;
            float Tw[9];
#pragma unroll
            for(int i=0;i<9;i++) Tw[i]=tr2s[i*9+j];
            float v=lg2s[j];
            al2s[j]=v;
            float lv=lg2s[9+j];
            for(int t=1;t<sl;++t){
                float lvn=lg2s[(t+1)*9+j];
                float q0=__shfl_sync(M9,v,0)+Tw[0], q1=__shfl_sync(M9,v,1)+Tw[1];
                float q2=__shfl_sync(M9,v,2)+Tw[2], q3=__shfl_sync(M9,v,3)+Tw[3];
                float q4=__shfl_sync(M9,v,4)+Tw[4], q5=__shfl_sync(M9,v,5)+Tw[5];
                float q6=__shfl_sync(M9,v,6)+Tw[6], q7=__shfl_sync(M9,v,7)+Tw[7];
                float q8=__shfl_sync(M9,v,8)+Tw[8];
                float m=fmaxf(fmaxf(fmaxf(q0,q1),fmaxf(q2,q3)),fmaxf(fmaxf(q4,q5),fmaxf(q6,q7)));
                v=fmaxf(m,q8)+lv;
                al2s[t*12+j]=v;
                lv=lvn;
            }
            int la=0; float best=-3.0e38f;
#pragma unroll
            for(int i=0;i<9;i++){float tot=__shfl_sync(M9,v,i); if(tot>best){best=tot;la=i;}}
            if(j==0) s_last2=la;
        }
    } else if(wid==1){ // ---- gold scores + decode1 + lognorm1 ----
        float s1=0.0f,s2=0.0f;
        for(int t=lane;t<sl;t+=32){
            int tg2=lab[t], tg1=(tg2>0)?1:0;
            s1+=lg1s[t*2+tg1]; s2+=lg2s[t*9+tg2];
            if(t>0){int tp2=lab[t-1],tp1=(tp2>0)?1:0; s1+=trans1[tp1*2+tg1]; s2+=tr2s[tp2*9+tg2];}
        }
#pragma unroll
        for(int o=16;o;o>>=1){s1+=__shfl_xor_sync(FULL,s1,o);s2+=__shfl_xor_sync(FULL,s2,o);}
        if(lane==0){
            s_g1=s1; s_g2=s2;
            // decode1 (exact, in-lane)
            float T00=trans1[0],T01=trans1[1],T10=trans1[2],T11=trans1[3];
            float a0=lg1s[0],a1=lg1s[1];
            for(int t=1;t<sl;++t){
                float2 lv=*(const float2*)(lg1s+2*t);
                float q00=a0+T00,q10=a1+T10,q01=a0+T01,q11=a1+T11;
                uchar2 bp; bp.x=(q10>q00)?1:0; bp.y=(q11>q01)?1:0;
                bp1[t]=bp;
                a0=fmaxf(q00,q10)+lv.x; a1=fmaxf(q01,q11)+lv.y;
            }
            s_last1=(a1>a0)?1:0;
            // lognorm1 (linear domain, in-lane)
            float F00=__expf(T00),F01=__expf(T01),F10=__expf(T10),F11=__expf(T11);
            float c0=el1s[0],c1v=el1s[1]; int Zi=0;
            for(int t=1;t<sl;++t){
                float2 e=*(const float2*)(el1s+2*t);
                float n0=(c0*F00+c1v*F10)*e.x, n1=(c0*F01+c1v*F11)*e.y;
                c0=n0; c1v=n1;
                if((t&7)==0){
                    int eb=(__float_as_int(c0)>>23)&0xff;
                    float sc=__int_as_float((254-eb)<<23);
                    c0*=sc; c1v*=sc; Zi+=eb-127;
                }
            }
            s_ln1=(float)Zi*0.6931471805599453f+__logf(c0+c1v);
        }
    } else { // ---- wid 2..7: lognorm2 chunk warps (matrix products, no shfl) ----
        int c=wid-2;
        if(lane<9){
            int i=lane;
            unsigned long long E2[9][5];
#pragma unroll
            for(int k=0;k<9;k++)
#pragma unroll
                for(int jp=0;jp<5;jp++)
                    E2[k][jp]=*reinterpret_cast<const unsigned long long*>(es+k*10+2*jp);
            int len=(sl+4)/6;
            int t0=1+c*len, t1=min(t0+len,sl);
            float p[9]; int Zi=0;
            if(t0<sl){
                const float* e0=el2s+t0*12;
#pragma unroll
                for(int j=0;j<9;j++) p[j]=es[i*10+j]*e0[j];
                int cnt=0;
                for(int t=t0+1;t<t1;++t){
                    const unsigned long long* er=reinterpret_cast<const unsigned long long*>(el2s+t*12);
                    unsigned long long a0=0,a1=0,a2=0,a3=0,a4=0;
#pragma unroll
                    for(int k=0;k<9;k++){
                        unsigned long long pk=pack2(p[k]);
                        a0=ffma2(pk,E2[k][0],a0); a1=ffma2(pk,E2[k][1],a1);
                        a2=ffma2(pk,E2[k][2],a2); a3=ffma2(pk,E2[k][3],a3);
                        a4=ffma2(pk,E2[k][4],a4);
                    }
                    a0=fmul2(a0,er[0]); a1=fmul2(a1,er[1]); a2=fmul2(a2,er[2]);
                    a3=fmul2(a3,er[3]); a4=fmul2(a4,er[4]);
                    float d8,junk;
                    unpack2(a0,p[0],p[1]); unpack2(a1,p[2],p[3]);
                    unpack2(a2,p[4],p[5]); unpack2(a3,p[6],p[7]);
                    unpack2(a4,d8,junk); p[8]=d8;
                    if(((++cnt)&7)==0){
                        float r0=__shfl_sync(M9,p[0],0);
                        int eb=(__float_as_int(r0)>>23)&0xff;
                        float sc=__int_as_float((254-eb)<<23);
#pragma unroll
                        for(int j=0;j<9;j++) p[j]*=sc;
                        Zi+=eb-127;
                    }
                }
            } else {
#pragma unroll
                for(int j=0;j<9;j++) p[j]=(i==j)?1.0f:0.0f;
            }
#pragma unroll
            for(int j=0;j<9;j++) Pc[c*81+i*9+j]=p[j];
            if(i==0) Zc[c]=Zi;
        }
    }
    __syncthreads();

    // ---- bp2 recompute from stored alphas (parallel, exact) ----
    for(int t=1+tid;t<sl;t+=256){
        const float4* ar=(const float4*)(al2s+(t-1)*12);
        float4 A=ar[0],Bv=ar[1],Cv=ar[2];
        float av[9]={A.x,A.y,A.z,A.w,Bv.x,Bv.y,Bv.z,Bv.w,Cv.x};
        unsigned char* bo=bp2+t*9;
#pragma unroll
        for(int j=0;j<9;j++){
            float q[9]; float m=-3.0e38f;
#pragma unroll
            for(int i=0;i<9;i++){q[i]=av[i]+tr2s[i*9+j]; m=fmaxf(m,q[i]);}
            int bp=8;
#pragma unroll
            for(int i=7;i>=0;i--) if(q[i]==m) bp=i;
            bo[j]=(unsigned char)bp;
        }
    }
    for(int t=sl+tid;t<T;t+=256){
        unsigned char* bo=bp2+t*9;
#pragma unroll
        for(int j=0;j<9;j++) bo[j]=(unsigned char)j;
        uchar2 e; e.x=0; e.y=1; bp1[t]=e;
    }
    // ---- lognorm2 combine (single thread, off critical path) ----
    if(tid==0){
        float al[9];
#pragma unroll
        for(int j=0;j<9;j++) al[j]=el2s[j];
        int Zt=0;
        for(int c=0;c<6;c++){
            float an[9];
#pragma unroll
            for(int j=0;j<9;j++){
                float s=0.0f;
#pragma unroll
                for(int k=0;k<9;k++) s=fmaf(al[k],Pc[c*81+k*9+j],s);
                an[j]=s;
            }
            int eb=(__float_as_int(an[0])>>23)&0xff;
            float sc=__int_as_float((254-eb)<<23);
#pragma unroll
            for(int j=0;j<9;j++) al[j]=an[j]*sc;
            Zt+=eb-127+Zc[c];
        }
        float s=0.0f;
#pragma unroll
        for(int j=0;j<9;j++) s+=al[j];
        s_ln2=(float)Zt*0.6931471805599453f+__logf(s);
    }
    __syncthreads();

    // ---- chunk tag-maps ----
    if(tid<63){
        int c=1+tid/9, j=tid-(tid/9)*9;
        int hi=(c==7)?511:64*(c+1);
        int cur=j;
        for(int t=hi;t>64*c;--t) cur=bp2[t*9+cur];
        map2[(c-1)*9+j]=(unsigned char)cur;
    } else if(tid>=64&&tid<78){
        int c=1+(tid-64)/2, j=(tid-64)&1;
        int hi=(c==7)?511:64*(c+1);
        int cur=j;
        for(int t=hi;t>64*c;--t){uchar2 bp=bp1[t]; cur=cur?bp.y:bp.x;}
        map1[(c-1)*2+j]=(unsigned char)cur;
    }
    __syncthreads();
    if(tid==0){
        int e=s_last2; ex2[7]=(unsigned char)e;
        for(int c=7;c>=1;c--){e=map2[(c-1)*9+e]; ex2[c-1]=(unsigned char)e;}
    } else if(tid==32){
        int e=s_last1; ex1[7]=(unsigned char)e;
        for(int c=7;c>=1;c--){e=map1[(c-1)*2+e]; ex1[c-1]=(unsigned char)e;}
    }
    __syncthreads();
    if(tid<8){
        int c=tid; int hi=(c==7)?511:64*(c+1); int cur=ex2[c];
        if(c==7) vit2[511]=(unsigned char)cur;
        for(int t=hi;t>64*c;--t){cur=bp2[t*9+cur]; vit2[t-1]=(unsigned char)cur;}
    } else if(tid>=32&&tid<40){
        int c=tid-32; int hi=(c==7)?511:64*(c+1); int cur=ex1[c];
        if(c==7) vit1[511]=(unsigned char)cur;
        for(int t=hi;t>64*c;--t){uchar2 bp=bp1[t]; cur=cur?bp.y:bp.x; vit1[t-1]=(unsigned char)cur;}
    }
    __syncthreads();

    // ---- outputs + accuracy partials ----
    float c1=0.0f,c2=0.0f,cc=0.0f;
    for(int t=tid;t<T;t+=256){
        int v1=vit1[t],v2=vit2[t],lb=lab[t];
        int vv=v1?v2:0;
        out[b*T+t]=(float)vv;
        if(t<sl){
            c1+=(v1==((lb>0)?1:0))?1.0f:0.0f;
            c2+=(v2==lb)?1.0f:0.0f;
            cc+=(vv==lb)?1.0f:0.0f;
        }
    }
#pragma unroll
    for(int o=16;o;o>>=1){
        c1+=__shfl_xor_sync(FULL,c1,o);
        c2+=__shfl_xor_sync(FULL,c2,o);
        cc+=__shfl_xor_sync(FULL,cc,o);
    }
    if(lane==0){sred[wid]=c1;sred[8+wid]=c2;sred[16+wid]=cc;}
    __syncthreads();
    if(tid==0){
        float a1=0,a2=0,a3=0;
#pragma unroll
        for(int k=0;k<8;k++){a1+=sred[k];a2+=sred[8+k];a3+=sred[16+k];}
        g_c1[b]=a1; g_c2[b]=a2; g_cc[b]=a3;
        g_ll1[b]=s_g1-s_ln1; g_ll2[b]=s_g2-s_ln2;
        __threadfence();
        int v=atomicAdd(&g_ctr,1);
        s_isLast=(v==B-1)?1:0;
    }
    __syncthreads();

    if(s_isLast){
        __threadfence();
        int i=tid;
        float vals[6]={0,0,0,0,0,0};
        if(i<B){
            vals[0]=-g_ll1[i]; vals[1]=-g_ll2[i];
            vals[2]=g_c1[i]; vals[3]=g_c2[i]; vals[4]=g_cc[i];
            vals[5]=(float)seqlen[i];
        }
#pragma unroll
        for(int k=0;k<6;k++)
#pragma unroll
            for(int o=16;o;o>>=1) vals[k]+=__shfl_xor_sync(FULL,vals[k],o);
        __shared__ float sh2[2][6];
        if(i<B&&(i&31)==0)
#pragma unroll
            for(int k=0;k<6;k++) sh2[i>>5][k]=vals[k];
        __syncthreads();
        if(i==0){
            float S[6];
#pragma unroll
            for(int k=0;k<6;k++) S[k]=sh2[0][k]+sh2[1][k];
            float loss=(S[0]/(float)B+8.0f*(S[1]/(float)B))/9.0f;
            float tot=S[5];
            int base=out_size-4;
            out[base+0]=loss;
            out[base+1]=S[2]/tot;
            out[base+2]=S[3]/tot;
            out[base+3]=S[4]/tot;
            g_ctr=0;
        }
    }
}

extern "C" void kernel_launch(void* const* d_in, const int* in_sizes, int n_in,
                              void* d_out, int out_size) {
    const float* x      = (const float*)d_in[0];
    const int*   label  = (const int*)d_in[1];
    const int*   seqlen = (const int*)d_in[2];
    const float* W1     = (const float*)d_in[3];
    const float* b1     = (const float*)d_in[4];
    const float* W2     = (const float*)d_in[5];
    const float* b2     = (const float*)d_in[6];
    const float* trans1 = (const float*)d_in[7];
    const float* trans2 = (const float*)d_in[8];
    float* out = (float*)d_out;

    static int smem_set = 0;
    if(!smem_set){
        cudaFuncSetAttribute(scan_kernel, cudaFuncAttributeMaxDynamicSharedMemorySize, SM_TOT);
        smem_set = 1;
    }
    gemm_kernel<<<256, 256>>>(x, W1, b1, W2, b2);
    scan_kernel<<<B, 256, SM_TOT>>>(label, seqlen, trans1, trans2, out, out_size);
}